// round 17
// baseline (speedup 1.0000x reference)
#include <cuda_runtime.h>
#include <cuda_bf16.h>
#include <cstdint>

// Problem constants (fixed by the reference setup)
#define B_    64
#define NA_   2048
#define EG_   40960             // directed edges per graph
#define E_    (B_ * EG_)        // 2,621,440 input edges
#define E2_   (2 * E_)          // 5,242,880 symmetrized edges

#define THREADS_  256
#define C_        256                 // edges per chunk (1 edge/thread/chunk)
#define BPG_      20                  // blocks per graph
#define CPB_      (EG_ / C_ / BPG_)   // 8 chunks per block
#define GRID_     (B_ * BPG_)         // 1280

// Output layout: tuple members flattened row-major and concatenated, cast to f32
#define BASE_EI   0
#define BASE_OFF  (2 * E2_)                 // 10,485,760
#define BASE_DIST (BASE_OFF + 3 * E2_)      // 26,214,400
#define BASE_VEC  (BASE_DIST + E2_)         // 31,457,280
#define BASE_NN   (BASE_VEC + 3 * E2_)      // 47,185,920
#define BASE_SWAP (BASE_NN + B_)            // 47,185,984

// Staged segments per buffer (floats): offF 3C | offW 3C | vecF 3C | vecW 3C
#define SEG_OFFF  (0 * C_)
#define SEG_OFFW  (3 * C_)
#define SEG_VECF  (6 * C_)
#define SEG_VECW  (9 * C_)
#define BUF_FL    (12 * C_)                       // 3072 floats = 12 KB

// Dynamic smem: [ float4 s_pos[NA_] | float stage[2][BUF_FL] ]
#define SM_POS_BYTES   (NA_ * 16)                 // 32768
#define SMEM_TOTAL     (SM_POS_BYTES + 2 * BUF_FL * 4)   // 57344 B -> 4 blocks/SM

__device__ __forceinline__ uint32_t smem_u32(const void* p) {
    uint32_t a;
    asm("{ .reg .u64 t; cvta.to.shared.u64 t, %1; cvt.u32.u64 %0, t; }" : "=r"(a) : "l"(p));
    return a;
}

__device__ __forceinline__ void bulk_store(float* gdst, uint32_t ssrc, uint32_t bytes) {
    asm volatile("cp.async.bulk.global.shared::cta.bulk_group [%0], [%1], %2;"
                 :: "l"(gdst), "r"(ssrc), "r"(bytes) : "memory");
}

__global__ __launch_bounds__(THREADS_, 4)
void graph_edges_kernel(const float* __restrict__ pos,
                        const float* __restrict__ cell,
                        const void*  __restrict__ ei_raw,
                        const int*   __restrict__ off,
                        const void*  __restrict__ nn_raw,
                        float*       __restrict__ out)
{
    extern __shared__ char smem[];
    float4* s_pos = (float4*)smem;
    float*  stg   = (float*)(smem + SM_POS_BYTES);
    __shared__ int s_is64;

    const int tid = threadIdx.x;
    const int blk = blockIdx.x;
    const int b   = blk / BPG_;             // graph id
    const int bg  = blk % BPG_;             // block index within graph

    if (tid == 0) {
        // dtype detection: true int64 indices < 2^31; int32 data read as u64
        // has a nonzero high half among the first 8 words w.o.p.
        const unsigned long long* eu = (const unsigned long long*)ei_raw;
        int is64 = 1;
        #pragma unroll
        for (int k = 0; k < 8; ++k)
            if (eu[k] >= (1ULL << 31)) { is64 = 0; break; }
        s_is64 = is64;
    }

    // Cooperative coalesced load of this graph's positions, padded to float4.
    {
        const float* pb = pos + (size_t)b * NA_ * 3;
        float* sp = (float*)s_pos;
        #pragma unroll
        for (int i = tid; i < NA_ * 3; i += THREADS_) {
            const int atom = i / 3;
            const int comp = i - atom * 3;
            sp[atom * 4 + comp] = pb[i];
        }
    }
    __syncthreads();
    const int is64 = s_is64;

    // cell[b] broadcast (L1-resident)
    const float* cb = cell + 9 * b;
    const float c00 = cb[0], c01 = cb[1], c02 = cb[2];
    const float c10 = cb[3], c11 = cb[4], c12 = cb[5];
    const float c20 = cb[6], c21 = cb[7], c22 = cb[8];

    const int abase = b * NA_;
    const int l = tid;
    const int ebase = b * EG_ + bg * CPB_ * C_;

    // num_neighbors_sym (one block only; tiny)
    if (blk == 0 && tid < B_) {
        long long v;
        if (is64) v = ((const long long*)nn_raw)[tid];
        else      v = (long long)((const int*)nn_raw)[tid];
        out[BASE_NN + tid] = (float)(2 * v);
    }

    // ---- prefetch chunk 0 inputs ----
    int iv, jv;
    float o0, o1, o2;
    {
        const int e = ebase + l;
        if (is64) {
            const long long* ei = (const long long*)ei_raw;
            iv = (int)__ldcs(&ei[e]);
            jv = (int)__ldcs(&ei[E_ + e]);
        } else {
            const int* ei = (const int*)ei_raw;
            iv = __ldcs(&ei[e]);
            jv = __ldcs(&ei[E_ + e]);
        }
        o0 = (float)__ldcs(&off[3 * e + 0]);
        o1 = (float)__ldcs(&off[3 * e + 1]);
        o2 = (float)__ldcs(&off[3 * e + 2]);
    }

    #pragma unroll 1
    for (int ci = 0; ci < CPB_; ++ci) {
        const int e0 = ebase + ci * C_;
        const int f0 = e0 + b * EG_;        // fwd run start (contiguous C_)
        const int w0 = f0 + EG_;            // bwd run start
        float* buf = stg + (ci & 1) * BUF_FL;

        // ---- compute from prefetched regs ----
        const float4 pi = s_pos[iv - abase];
        const float4 pj = s_pos[jv - abase];
        const float dx = pi.x - pj.x + (o0 * c00 + o1 * c10 + o2 * c20);
        const float dy = pi.y - pj.y + (o0 * c01 + o1 * c11 + o2 * c21);
        const float dz = pi.z - pj.z + (o0 * c02 + o1 * c12 + o2 * c22);
        const float dist = sqrtf(dx * dx + dy * dy + dz * dz);
        const float n = -1.0f / dist;
        const float vx = dx * n, vy = dy * n, vz = dz * n;
        const float fiv = (float)iv, fjv = (float)jv;
        const float g0 = o0, g1 = o1, g2 = o2;

        // ---- direct coalesced stores for stride-1 arrays (cheap STG.32) ----
        __stcs(&out[BASE_EI + f0 + l],        fiv);
        __stcs(&out[BASE_EI + E2_ + f0 + l],  fjv);
        __stcs(&out[BASE_EI + w0 + l],        fjv);
        __stcs(&out[BASE_EI + E2_ + w0 + l],  fiv);
        __stcs(&out[BASE_DIST + f0 + l], dist);
        __stcs(&out[BASE_DIST + w0 + l], dist);
        __stcs(&out[BASE_SWAP + f0 + l], (float)(w0 + l));
        __stcs(&out[BASE_SWAP + w0 + l], (float)(f0 + l));

        // ---- buffer reuse: chunk ci-2's TMA reads must be done (read 1 leaves
        //      ci-1 outstanding). Per-thread groups -> issuing threads wait. ----
        if (ci >= 2) {
            if (tid < 4)
                asm volatile("cp.async.bulk.wait_group.read 1;" ::: "memory");
            __syncthreads();
        }

        // ---- stage stride-3 arrays (conflict-free: 3l mod 32 bijective) ----
        buf[SEG_OFFF + 3 * l + 0] = g0;
        buf[SEG_OFFF + 3 * l + 1] = g1;
        buf[SEG_OFFF + 3 * l + 2] = g2;
        buf[SEG_OFFW + 3 * l + 0] = -g0;
        buf[SEG_OFFW + 3 * l + 1] = -g1;
        buf[SEG_OFFW + 3 * l + 2] = -g2;
        buf[SEG_VECF + 3 * l + 0] = vx;
        buf[SEG_VECF + 3 * l + 1] = vy;
        buf[SEG_VECF + 3 * l + 2] = vz;
        buf[SEG_VECW + 3 * l + 0] = -vx;
        buf[SEG_VECW + 3 * l + 1] = -vy;
        buf[SEG_VECW + 3 * l + 2] = -vz;

        __syncthreads();

        // ---- parallel TMA issue: one segment per thread (tids 0-3) ----
        if (tid < 4) {
            asm volatile("fence.proxy.async.shared::cta;" ::: "memory");
            const uint32_t sbuf = smem_u32(buf);
            const uint32_t SEGB = 3 * C_ * 4;   // 3072 B per segment
            if      (tid == 0) bulk_store(out + BASE_OFF + 3 * f0, sbuf + SEG_OFFF * 4, SEGB);
            else if (tid == 1) bulk_store(out + BASE_OFF + 3 * w0, sbuf + SEG_OFFW * 4, SEGB);
            else if (tid == 2) bulk_store(out + BASE_VEC + 3 * f0, sbuf + SEG_VECF * 4, SEGB);
            else               bulk_store(out + BASE_VEC + 3 * w0, sbuf + SEG_VECW * 4, SEGB);
            asm volatile("cp.async.bulk.commit_group;" ::: "memory");
        }

        // ---- prefetch next chunk's inputs (full chunk period to land) ----
        if (ci + 1 < CPB_) {
            const int en = e0 + C_ + l;
            if (is64) {
                const long long* ei = (const long long*)ei_raw;
                iv = (int)__ldcs(&ei[en]);
                jv = (int)__ldcs(&ei[E_ + en]);
            } else {
                const int* ei = (const int*)ei_raw;
                iv = __ldcs(&ei[en]);
                jv = __ldcs(&ei[E_ + en]);
            }
            o0 = (float)__ldcs(&off[3 * en + 0]);
            o1 = (float)__ldcs(&off[3 * en + 1]);
            o2 = (float)__ldcs(&off[3 * en + 2]);
        }
    }

    // Drain outstanding TMA smem reads before CTA teardown.
    if (tid < 4)
        asm volatile("cp.async.bulk.wait_group.read 0;" ::: "memory");
    __syncthreads();
}

extern "C" void kernel_launch(void* const* d_in, const int* in_sizes, int n_in,
                              void* d_out, int out_size) {
    const float* pos  = (const float*)d_in[0];   // [N,3] f32
    const float* cell = (const float*)d_in[1];   // [B,3,3] f32
    const void*  ei   = d_in[2];                 // [2,E] int64 or int32
    const int*   off  = (const int*)d_in[3];     // [E,3] int32
    const void*  nn   = d_in[4];                 // [B] int64 or int32
    float* out = (float*)d_out;

    cudaFuncSetAttribute(graph_edges_kernel,
                         cudaFuncAttributeMaxDynamicSharedMemorySize, SMEM_TOTAL);
    graph_edges_kernel<<<GRID_, THREADS_, SMEM_TOTAL>>>(pos, cell, ei, off, nn, out);
}